// round 16
// baseline (speedup 1.0000x reference)
#include <cuda_runtime.h>
#include <cuda_fp16.h>
#include <cstdint>

#define MAXN 100000
#define MAXE 1700000
#define FDIM 64
#define NB_MAX ((MAXN + 255) / 256)   // 391

// Scratch — __device__ globals, referenced DIRECTLY in kernels.
__device__ int    g_is64;           // 1 if edge_index is int64, 0 if int32
__device__ int    g_cnt[MAXN];
__device__ int    g_off[MAXN + 1];
__device__ int    g_cursor[MAXN];
__device__ int    g_srcs[MAXE];
__device__ int    g_blockoff[NB_MAX];
__device__ float  g_dinv[MAXN];
__device__ __half g_H1h[(size_t)MAXN * FDIM];   // fp16 hidden, layer 1
__device__ __half g_agg1h[(size_t)MAXN * FDIM]; // fp16 layer-1 aggregate
__device__ __half g_H2h[(size_t)MAXN * FDIM];   // fp16 hidden, layer 2

// ---------------------------------------------------------------------------
// init: detect edge dtype (thread 0) + zero g_cnt.
// ---------------------------------------------------------------------------
__global__ void init_kernel(const unsigned int* __restrict__ raw, int M, int E) {
    int i = blockIdx.x * blockDim.x + threadIdx.x;
    if (i < M) g_cnt[i] = 0;
    if (i == 0) {
        int nz = 0;
        int lim = E < 64 ? E : 64;
        for (int k = 0; k < lim; k++)
            if (raw[2 * k + 1] != 0u) nz++;
        g_is64 = (nz == 0) ? 1 : 0;
    }
}

// ---------------------------------------------------------------------------
// count: 4 edges per thread, vectorized loads.
// ---------------------------------------------------------------------------
__global__ void count_kernel(const void* __restrict__ ei, int E) {
    int t = blockIdx.x * blockDim.x + threadIdx.x;
    int e0 = t * 4;
    if (e0 >= E) return;
    int n = min(4, E - e0);
    int c[4];
    if (g_is64) {
        const long long* p = (const long long*)ei + E + e0;
        if (n == 4) {
            longlong2 a = *(const longlong2*)p;
            longlong2 b = *(const longlong2*)(p + 2);
            c[0] = (int)a.x; c[1] = (int)a.y; c[2] = (int)b.x; c[3] = (int)b.y;
        } else {
            for (int i = 0; i < n; i++) c[i] = (int)p[i];
        }
    } else {
        const int* p = (const int*)ei + E + e0;
        if (n == 4) {
            int4 a = *(const int4*)p;
            c[0] = a.x; c[1] = a.y; c[2] = a.z; c[3] = a.w;
        } else {
            for (int i = 0; i < n; i++) c[i] = p[i];
        }
    }
    for (int i = 0; i < n; i++) atomicAdd(&g_cnt[c[i]], 1);
}

// --- grid-wide exclusive scan of g_cnt -> g_off ---
__global__ void scan_a_kernel(int M) {
    __shared__ int sh[256];
    int tid = threadIdx.x;
    int i = blockIdx.x * 256 + tid;
    int v = (i < M) ? g_cnt[i] : 0;
    if (i < M) g_dinv[i] = rsqrtf((float)(v + 1));
    sh[tid] = v;
    __syncthreads();
#pragma unroll
    for (int d = 128; d > 0; d >>= 1) {
        if (tid < d) sh[tid] += sh[tid + d];
        __syncthreads();
    }
    if (tid == 0) g_blockoff[blockIdx.x] = sh[0];
}

// scan_b: 128 threads, warp-shuffle scan of NB block sums.
__global__ void scan_b_kernel(int NB, int M) {
    __shared__ int warp_tot[4];
    int tid = threadIdx.x;
    int lane = tid & 31, warp = tid >> 5;
    int nper = (NB + 127) / 128;
    int start = tid * nper;
    int local[8];
    int s = 0;
    for (int i = 0; i < nper; i++) {
        int idx = start + i;
        int v = (idx < NB) ? g_blockoff[idx] : 0;
        local[i] = v; s += v;
    }
    int incl = s;
#pragma unroll
    for (int d = 1; d < 32; d <<= 1) {
        int t = __shfl_up_sync(0xffffffffu, incl, d);
        if (lane >= d) incl += t;
    }
    if (lane == 31) warp_tot[warp] = incl;
    __syncthreads();
    int woff = 0;
    for (int w = 0; w < warp; w++) woff += warp_tot[w];
    int run = woff + incl - s;
    for (int i = 0; i < nper; i++) {
        int idx = start + i;
        if (idx < NB) { g_blockoff[idx] = run; run += local[i]; }
    }
    if (tid == 127) g_off[M] = run;
}

__global__ void scan_c_kernel(int M) {
    __shared__ int sh[256];
    int tid = threadIdx.x;
    int i = blockIdx.x * 256 + tid;
    int v = (i < M) ? g_cnt[i] : 0;
    sh[tid] = v;
    __syncthreads();
    for (int d = 1; d < 256; d <<= 1) {
        int t = (tid >= d) ? sh[tid - d] : 0;
        __syncthreads();
        sh[tid] += t;
        __syncthreads();
    }
    if (i < M) {
        int pos = g_blockoff[blockIdx.x] + sh[tid] - v;
        g_off[i] = pos;
        g_cursor[i] = pos;
    }
}

// ---------------------------------------------------------------------------
// fill: 4 edges per thread, vectorized loads.
// ---------------------------------------------------------------------------
__global__ void fill_kernel(const void* __restrict__ ei, int E) {
    int t = blockIdx.x * blockDim.x + threadIdx.x;
    int e0 = t * 4;
    if (e0 >= E) return;
    int n = min(4, E - e0);
    int r[4], c[4];
    if (g_is64) {
        const long long* pr = (const long long*)ei + e0;
        const long long* pc = (const long long*)ei + E + e0;
        if (n == 4) {
            longlong2 a = *(const longlong2*)pr;
            longlong2 b = *(const longlong2*)(pr + 2);
            longlong2 x = *(const longlong2*)pc;
            longlong2 y = *(const longlong2*)(pc + 2);
            r[0] = (int)a.x; r[1] = (int)a.y; r[2] = (int)b.x; r[3] = (int)b.y;
            c[0] = (int)x.x; c[1] = (int)x.y; c[2] = (int)y.x; c[3] = (int)y.y;
        } else {
            for (int i = 0; i < n; i++) { r[i] = (int)pr[i]; c[i] = (int)pc[i]; }
        }
    } else {
        const int* pr = (const int*)ei + e0;
        const int* pc = (const int*)ei + E + e0;
        if (n == 4) {
            int4 a = *(const int4*)pr;
            int4 x = *(const int4*)pc;
            r[0] = a.x; r[1] = a.y; r[2] = a.z; r[3] = a.w;
            c[0] = x.x; c[1] = x.y; c[2] = x.z; c[3] = x.w;
        } else {
            for (int i = 0; i < n; i++) { r[i] = pr[i]; c[i] = pc[i]; }
        }
    }
    for (int i = 0; i < n; i++) {
        int pos = atomicAdd(&g_cursor[c[i]], 1);
        g_srcs[pos] = r[i];
    }
}

// ---------------------------------------------------------------------------
// Tensor-core GEMM (HMMA), full-K XOR-swizzled smem, warp-per-row staging
// (each warp-LDG is a contiguous 512B span -> 4 full 128B wavefronts).
// ---------------------------------------------------------------------------
__device__ __forceinline__ void ldsm_x4(unsigned* r, uint32_t addr) {
    asm volatile("ldmatrix.sync.aligned.m8n8.x4.shared.b16 {%0,%1,%2,%3}, [%4];"
                 : "=r"(r[0]), "=r"(r[1]), "=r"(r[2]), "=r"(r[3]) : "r"(addr));
}
__device__ __forceinline__ void ldsm_x2_trans(unsigned* r, uint32_t addr) {
    asm volatile("ldmatrix.sync.aligned.m8n8.x2.trans.shared.b16 {%0,%1}, [%2];"
                 : "=r"(r[0]), "=r"(r[1]) : "r"(addr));
}
__device__ __forceinline__ void mma16816(float* d, const unsigned* a,
                                         const unsigned* b) {
    asm volatile(
        "mma.sync.aligned.m16n8k16.row.col.f32.f16.f16.f32 "
        "{%0,%1,%2,%3}, {%4,%5,%6,%7}, {%8,%9}, {%0,%1,%2,%3};"
        : "+f"(d[0]), "+f"(d[1]), "+f"(d[2]), "+f"(d[3])
        : "r"(a[0]), "r"(a[1]), "r"(a[2]), "r"(a[3]), "r"(b[0]), "r"(b[1]));
}

template <int K, bool LAYER2>
__global__ void __launch_bounds__(256, 4)
gcn_gemm_kernel(const float* __restrict__ Xin, const float* __restrict__ W,
                int M) {
    __half* Hout = LAYER2 ? g_H2h : g_H1h;

    __shared__ __half As[128 * K];
    __shared__ __half Bs[K * 64];

    const int tid  = threadIdx.x;
    const int warp = tid >> 5;
    const int lane = tid & 31;
    const int row0 = blockIdx.x * 128;
    const int wm0  = warp * 16;

    float acc[8][4];
#pragma unroll
    for (int nf = 0; nf < 8; nf++)
#pragma unroll
        for (int q = 0; q < 4; q++) acc[nf][q] = 0.0f;

    const uint32_t a_base = (uint32_t)__cvta_generic_to_shared(&As[0]);
    const uint32_t b_base = (uint32_t)__cvta_generic_to_shared(&Bs[0]);

    // ---- Stage A: warp-per-row spans ----
    if (LAYER2) {
        // fp16 agg1h: 128 rows x 8 uint4; warp covers 4 contiguous rows (512B)
        const __half2 z2 = __float2half2_rn(0.f);
#pragma unroll
        for (int t = 0; t < 4; t++) {
            int idx = tid + t * 256;
            int r = idx >> 3;
            int c16 = idx & 7;
            int row = row0 + r;
            uint4 hv = make_uint4(0u, 0u, 0u, 0u);
            if (row < M)
                hv = *(const uint4*)&g_agg1h[(size_t)row * 64 + c16 * 8];
            __half2* h2 = (__half2*)&hv;
#pragma unroll
            for (int q = 0; q < 4; q++) h2[q] = __hmax2(h2[q], z2);
            *(uint4*)&As[r * K + (c16 ^ (r & 7)) * 8] = hv;
        }
    } else {
        // fp32 X: 128 rows x 32 float4; warp = exactly one row (512B)
#pragma unroll
        for (int t = 0; t < 16; t++) {
            int idx = tid + t * 256;
            int r = idx >> 5;
            int f4 = idx & 31;
            int row = row0 + r;
            float4 v = make_float4(0.f, 0.f, 0.f, 0.f);
            if (row < M)
                v = *(const float4*)&Xin[(size_t)row * K + f4 * 4];
            uint2 st;
            __half2* h2 = (__half2*)&st;
            h2[0] = __floats2half2_rn(v.x, v.y);
            h2[1] = __floats2half2_rn(v.z, v.w);
            int c16 = f4 >> 1;
            *(uint2*)&As[r * K + (c16 ^ (r & 7)) * 8 + (f4 & 1) * 4] = st;
        }
    }
    // ---- Stage B: K rows x 16 float4; warp = 2 contiguous rows (512B) ----
#pragma unroll
    for (int t = 0; t < K * 16 / 256; t++) {
        int idx = tid + t * 256;
        int kr = idx >> 4;
        int f4 = idx & 15;
        float4 v = *(const float4*)&W[(size_t)kr * 64 + f4 * 4];
        uint2 st;
        __half2* h2 = (__half2*)&st;
        h2[0] = __floats2half2_rn(v.x, v.y);
        h2[1] = __floats2half2_rn(v.z, v.w);
        int c16 = f4 >> 1;
        *(uint2*)&Bs[kr * 64 + (c16 ^ (kr & 7)) * 8 + (f4 & 1) * 4] = st;
    }
    __syncthreads();

    // ---- MMA over full K ----
#pragma unroll
    for (int ks = 0; ks < K / 16; ks++) {
        unsigned a[4];
        int arow = wm0 + (lane & 15);
        int ac16 = ks * 2 + (lane >> 4);
        uint32_t a_addr = a_base + ((arow * K + (ac16 ^ (arow & 7)) * 8) << 1);
        ldsm_x4(a, a_addr);
#pragma unroll
        for (int nf = 0; nf < 8; nf++) {
            unsigned b[2];
            int kr = ks * 16 + (lane & 15);
            uint32_t b_addr = b_base + ((kr * 64 + ((nf ^ (kr & 7)) * 8)) << 1);
            ldsm_x2_trans(b, b_addr);
            mma16816(acc[nf], a, b);
        }
    }

    // Epilogue: D-fragment mapping -> fp16 H
    const int tig = lane & 3;
    const int grp = lane >> 2;
    const int r0 = row0 + wm0 + grp;
    const int r1 = r0 + 8;
#pragma unroll
    for (int nf = 0; nf < 8; nf++) {
        int col = nf * 8 + tig * 2;
        if (r0 < M) {
            __half2 h = __floats2half2_rn(acc[nf][0], acc[nf][1]);
            *(__half2*)&Hout[(size_t)r0 * 64 + col] = h;
        }
        if (r1 < M) {
            __half2 h = __floats2half2_rn(acc[nf][2], acc[nf][3]);
            *(__half2*)&Hout[(size_t)r1 * 64 + col] = h;
        }
    }
}

// ---------------------------------------------------------------------------
// CSR gather, WARP-PER-NODE: all 32 lanes read the SAME 128B H row per edge
// (1 L1tex wavefront/edge vs 16 wf/4 edges before). Lane owns channels
// {2*lane, 2*lane+1} as one half2 (uint). fp32 accumulate, 4x unroll.
//   agg[n] = bias + dinv[n]*( dinv[n]*H[n] + sum_src dinv[src]*H[src] )
// ---------------------------------------------------------------------------
template <bool LAYER2>
__global__ void gather_kernel(const float* __restrict__ bias,
                              float* __restrict__ OUT, int M) {
    const unsigned* Hu = (const unsigned*)(LAYER2 ? g_H2h : g_H1h);

    int n = (blockIdx.x * blockDim.x + threadIdx.x) >> 5;
    if (n >= M) return;
    int lane = threadIdx.x & 31;

    float dn = g_dinv[n];
    float a0, a1;
    {
        unsigned u = Hu[(size_t)n * 32 + lane];      // self half2
        float2 f = __half22float2(*(__half2*)&u);
        a0 = dn * f.x; a1 = dn * f.y;
    }

    int s = g_off[n], e = g_off[n + 1];
    int j = s;
    for (; j + 3 < e; j += 4) {
        int r0 = g_srcs[j],     r1 = g_srcs[j + 1];
        int r2 = g_srcs[j + 2], r3 = g_srcs[j + 3];
        float w0 = g_dinv[r0], w1 = g_dinv[r1];
        float w2 = g_dinv[r2], w3 = g_dinv[r3];
        unsigned u0 = Hu[(size_t)r0 * 32 + lane];
        unsigned u1 = Hu[(size_t)r1 * 32 + lane];
        unsigned u2 = Hu[(size_t)r2 * 32 + lane];
        unsigned u3 = Hu[(size_t)r3 * 32 + lane];
        float2 f0 = __half22float2(*(__half2*)&u0);
        float2 f1 = __half22float2(*(__half2*)&u1);
        float2 f2 = __half22float2(*(__half2*)&u2);
        float2 f3 = __half22float2(*(__half2*)&u3);
        a0 += w0 * f0.x + w1 * f1.x + w2 * f2.x + w3 * f3.x;
        a1 += w0 * f0.y + w1 * f1.y + w2 * f2.y + w3 * f3.y;
    }
    for (; j < e; j++) {
        int r = g_srcs[j];
        float w = g_dinv[r];
        unsigned u = Hu[(size_t)r * 32 + lane];
        float2 f = __half22float2(*(__half2*)&u);
        a0 += w * f.x; a1 += w * f.y;
    }

    float2 bv = *(const float2*)&bias[lane * 2];
    float o0 = bv.x + dn * a0;
    float o1 = bv.y + dn * a1;

    if (LAYER2) {
        *(float2*)&OUT[(size_t)n * 64 + lane * 2] = make_float2(o0, o1);
    } else {
        __half2 hh = __floats2half2_rn(o0, o1);
        *(__half2*)&g_agg1h[(size_t)n * 64 + lane * 2] = hh;
    }
}

// ---------------------------------------------------------------------------
extern "C" void kernel_launch(void* const* d_in, const int* in_sizes, int n_in,
                              void* d_out, int out_size) {
    const float* x  = (const float*)d_in[0];
    const void*  ei = d_in[1];
    const float* W1 = (const float*)d_in[2];
    const float* b1 = (const float*)d_in[3];
    const float* W2 = (const float*)d_in[4];
    const float* b2 = (const float*)d_in[5];
    float*       out = (float*)d_out;

    const int M = in_sizes[0] / 128;   // 100000
    const int E = in_sizes[1] / 2;     // 1600000
    const int NB = (M + 255) / 256;
    const int T = 256;
    const int E4 = (E + 3) / 4;
    const int GB = (M + 7) / 8;        // gather blocks: 8 warps = 8 nodes each

    // 1-3: dtype detect + counts + dinv/scanA
    init_kernel<<<(M + T - 1) / T, T>>>((const unsigned int*)ei, M, E);
    count_kernel<<<(E4 + T - 1) / T, T>>>(ei, E);
    scan_a_kernel<<<NB, 256>>>(M);
    // 4: layer-1 GEMM (tensor cores) — ncu capture slot
    gcn_gemm_kernel<128, false><<<(M + 127) / 128, T>>>(x, W1, M);
    // 5-7: CSR offsets + fill
    scan_b_kernel<<<1, 128>>>(NB, M);
    scan_c_kernel<<<NB, 256>>>(M);
    fill_kernel<<<(E4 + T - 1) / T, T>>>(ei, E);
    // 8: layer-1 aggregate (fp16 out), warp-per-node
    gather_kernel<false><<<GB, T>>>(b1, nullptr, M);
    // 9-10: layer 2 (gather writes d_out fp32)
    gcn_gemm_kernel<64, true><<<(M + 127) / 128, T>>>(nullptr, W2, M);
    gather_kernel<true><<<GB, T>>>(b2, out, M);
}